// round 1
// baseline (speedup 1.0000x reference)
#include <cuda_runtime.h>
#include <cuda_bf16.h>
#include <cstdint>

#define FULLMASK 0xffffffffu
#define EMPTYV 3.402823466e38f

constexpr int Bc = 8, Nc = 16384, Fc = 32, Sc = 2048, Kc = 32, OUTc = 128;

// Scratch (device globals: allocation-free)
__device__ float g_xsq[Bc * Nc];
__device__ int   g_knn[Bc * Sc * Kc];

// ---------------------------------------------------------------------------
// Kernel 1: x_sq[b][n] = sum_f x^2
// ---------------------------------------------------------------------------
__global__ void xsq_kernel(const float* __restrict__ x) {
    int i = blockIdx.x * blockDim.x + threadIdx.x;
    if (i >= Bc * Nc) return;
    const float4* p = (const float4*)(x + (size_t)i * Fc);
    float s = 0.f;
#pragma unroll
    for (int c = 0; c < 8; ++c) {
        float4 v = p[c];
        s += v.x * v.x + v.y * v.y + v.z * v.z + v.w * v.w;
    }
    g_xsq[i] = s;
}

// ---------------------------------------------------------------------------
// Kernel 2: sampled_batch output [B, F, S]
// ---------------------------------------------------------------------------
__global__ void sampled_kernel(const float* __restrict__ x,
                               const int* __restrict__ sidx,
                               float* __restrict__ out2) {
    int i = blockIdx.x * blockDim.x + threadIdx.x;
    if (i >= Bc * Fc * Sc) return;
    int b = i / (Fc * Sc);
    int r = i - b * Fc * Sc;
    int f = r / Sc;
    int s = r - f * Sc;
    int row = sidx[b * Sc + s];
    out2[i] = x[((size_t)(b * Nc + row)) * Fc + f];
}

// ---------------------------------------------------------------------------
// Warp-level bitonic helpers for top-32 maintenance
// ---------------------------------------------------------------------------
__device__ __forceinline__ void cmpSwap(float& d, int& i, int j, bool dirAsc, int lane) {
    float od = __shfl_xor_sync(FULLMASK, d, j);
    int   oi = __shfl_xor_sync(FULLMASK, i, j);
    bool lower = ((lane & j) == 0);
    bool less = (d < od) || (d == od && i < oi);
    bool keep = dirAsc ? (lower == less) : (lower != less);
    if (!keep) { d = od; i = oi; }
}

__device__ __forceinline__ void sortDesc32(float& d, int& i, int lane) {
#pragma unroll
    for (int k = 2; k <= 32; k <<= 1) {
#pragma unroll
        for (int j = k >> 1; j > 0; j >>= 1) {
            bool asc = ((lane & k) == 0);
            cmpSwap(d, i, j, !asc, lane);   // inverted -> final descending
        }
    }
}

// cur (ascending across lanes) <- smallest-32 of (cur  U  buf); buf cleared
__device__ __forceinline__ void mergeTop(float& cd, int& ci, float& bd, int& bi, int lane) {
    sortDesc32(bd, bi, lane);
    bool takeNew = (bd < cd) || (bd == cd && bi < ci);
    float nd = takeNew ? bd : cd;
    int   ni = takeNew ? bi : ci;
#pragma unroll
    for (int j = 16; j > 0; j >>= 1) cmpSwap(nd, ni, j, true, lane);
    cd = nd; ci = ni;
    bd = EMPTYV; bi = 0;
}

// ---------------------------------------------------------------------------
// Kernel 3: fused distance + top-K.  Block: 256 thr, 8 warps, 4 queries/warp.
// grid = B*S/32 = 512 blocks.
// ---------------------------------------------------------------------------
__global__ __launch_bounds__(256) void knn_kernel(const float* __restrict__ x,
                                                  const int* __restrict__ sidx) {
    __shared__ float q_s[32][32];
    __shared__ float sq_s[32];
    __shared__ float xb[128 * 32];   // SW128-swizzled tile
    __shared__ float xsq_s[128];

    int b = blockIdx.x >> 6;                // 64 blocks per batch
    int qbase = (blockIdx.x & 63) * 32;
    int tid = threadIdx.x, lane = tid & 31, w = tid >> 5;

    // gather the 32 query points (one float4 per thread)
    {
        int q = tid >> 3, p = tid & 7;
        int row = sidx[b * Sc + qbase + q];
        float4 v = *(const float4*)(x + ((size_t)(b * Nc + row)) * Fc + p * 4);
        *(float4*)&q_s[q][p * 4] = v;
    }
    __syncthreads();
    if (tid < 32) {
        float s = 0.f;
#pragma unroll
        for (int f = 0; f < 32; ++f) { float v = q_s[tid][f]; s += v * v; }
        sq_s[tid] = s;
    }
    __syncthreads();

    int wq = w * 4;
    float sq[4];
#pragma unroll
    for (int qi = 0; qi < 4; ++qi) sq[qi] = sq_s[wq + qi];

    float cur_d[4], buf_d[4];
    int   cur_i[4], buf_i[4];
#pragma unroll
    for (int qi = 0; qi < 4; ++qi) {
        cur_d[qi] = EMPTYV; cur_i[qi] = 0;
        buf_d[qi] = EMPTYV; buf_i[qi] = 0;
    }

    for (int n0 = 0; n0 < Nc; n0 += 128) {
        __syncthreads();
        // load 128-point tile, swizzled (4 float4 per thread)
#pragma unroll
        for (int it = 0; it < 4; ++it) {
            int t = tid + it * 256;
            int r = t >> 3, p = t & 7;
            float4 v = *(const float4*)(x + ((size_t)(b * Nc + n0 + r)) * Fc + p * 4);
            int off = r * 128 + p * 16;
            off ^= (off >> 3) & 0x70;
            *(float4*)((char*)xb + off) = v;
        }
        if (tid < 128) xsq_s[tid] = g_xsq[b * Nc + n0 + tid];
        __syncthreads();

#pragma unroll
        for (int sub = 0; sub < 4; ++sub) {
            int c = sub * 32 + lane;
            float acc[4] = {0.f, 0.f, 0.f, 0.f};
#pragma unroll
            for (int p = 0; p < 8; ++p) {
                int off = c * 128 + p * 16;
                off ^= (off >> 3) & 0x70;
                float4 xv = *(const float4*)((const char*)xb + off);
#pragma unroll
                for (int qi = 0; qi < 4; ++qi) {
                    float4 qv = *(const float4*)&q_s[wq + qi][p * 4];
                    acc[qi] = fmaf(xv.x, qv.x, acc[qi]);
                    acc[qi] = fmaf(xv.y, qv.y, acc[qi]);
                    acc[qi] = fmaf(xv.z, qv.z, acc[qi]);
                    acc[qi] = fmaf(xv.w, qv.w, acc[qi]);
                }
            }
            float xq = xsq_s[c];
            int gi = n0 + c;
#pragma unroll
            for (int qi = 0; qi < 4; ++qi) {
                float d = sq[qi] + xq - 2.f * acc[qi];
                float thr = __shfl_sync(FULLMASK, cur_d[qi], 31);
                bool beat = d < thr;
                bool occ = buf_d[qi] < EMPTYV;
                if (__ballot_sync(FULLMASK, beat && occ)) {
                    mergeTop(cur_d[qi], cur_i[qi], buf_d[qi], buf_i[qi], lane);
                    thr = __shfl_sync(FULLMASK, cur_d[qi], 31);
                    beat = d < thr;
                }
                if (beat) { buf_d[qi] = d; buf_i[qi] = gi; }
            }
        }
    }

    // final flush + write neighbor indices
#pragma unroll
    for (int qi = 0; qi < 4; ++qi) {
        bool occ = buf_d[qi] < EMPTYV;
        if (__ballot_sync(FULLMASK, occ))
            mergeTop(cur_d[qi], cur_i[qi], buf_d[qi], buf_i[qi], lane);
        g_knn[(b * Sc + qbase + wq + qi) * Kc + lane] = cur_i[qi];
    }
}

// ---------------------------------------------------------------------------
// Kernel 4: gather neighbors, 2-layer pointwise MLP, max-pool over K.
// Persistent grid-stride blocks; weights re-laid-out once per block into
// channel-interleaved float4 smem.  Block: 256 thr = 8 warps, 4 neighbors/warp.
// ---------------------------------------------------------------------------
constexpr int SMEM_MLP = (32 * 32 + 128 * 32 + 32) * (int)sizeof(float4)
                       + (32 * 32 + 8 * 128) * (int)sizeof(float);

__global__ __launch_bounds__(256) void mlp_kernel(const float* __restrict__ x,
                                                  const float* __restrict__ W1,
                                                  const float* __restrict__ b1,
                                                  const float* __restrict__ W2,
                                                  const float* __restrict__ b2,
                                                  float* __restrict__ feat) {
    extern __shared__ char smem_raw[];
    float4* W1i = (float4*)smem_raw;          // [f][lane] -> chans l,l+32,l+64,l+96
    float4* W2i = W1i + 32 * 32;              // [o][lane]
    float4* b1i = W2i + 128 * 32;             // [lane]
    float*  g_s = (float*)(b1i + 32);         // [k][f]
    float*  red = g_s + 32 * 32;              // [w][o]

    int tid = threadIdx.x, lane = tid & 31, w = tid >> 5;

    for (int t = tid; t < 4096; t += 256) {
        int f = t >> 7, l = (t >> 2) & 31, j = t & 3;
        ((float*)&W1i[f * 32 + l])[j] = W1[(l + 32 * j) * Fc + f];
    }
    for (int t = tid; t < 16384; t += 256) {
        int o = t >> 7, l = (t >> 2) & 31, j = t & 3;
        ((float*)&W2i[o * 32 + l])[j] = W2[(l + 32 * j) * OUTc + o];
    }
    if (tid < 32)
        b1i[tid] = make_float4(b1[tid], b1[tid + 32], b1[tid + 64], b1[tid + 96]);

    for (int q = blockIdx.x; q < Bc * Sc; q += gridDim.x) {
        int b = q / Sc;
        int s = q - b * Sc;
        __syncthreads();   // protects g_s / red reuse + first-iter weight build
        {
            int k = tid >> 3, p = tid & 7;
            int row = g_knn[q * Kc + k];
            float4 v = *(const float4*)(x + ((size_t)(b * Nc + row)) * Fc + p * 4);
            *(float4*)&g_s[k * 32 + p * 4] = v;
        }
        __syncthreads();

        float4 m = make_float4(-EMPTYV, -EMPTYV, -EMPTYV, -EMPTYV);
#pragma unroll
        for (int pr = 0; pr < 2; ++pr) {
            int k0 = w * 4 + pr * 2;
            float4 bb = b1i[lane];
            float4 h0 = bb, h1v = bb;
#pragma unroll
            for (int f = 0; f < 32; ++f) {
                float4 w4 = W1i[f * 32 + lane];
                float ga = g_s[k0 * 32 + f];
                float gb = g_s[(k0 + 1) * 32 + f];
                h0.x = fmaf(w4.x, ga, h0.x);  h1v.x = fmaf(w4.x, gb, h1v.x);
                h0.y = fmaf(w4.y, ga, h0.y);  h1v.y = fmaf(w4.y, gb, h1v.y);
                h0.z = fmaf(w4.z, ga, h0.z);  h1v.z = fmaf(w4.z, gb, h1v.z);
                h0.w = fmaf(w4.w, ga, h0.w);  h1v.w = fmaf(w4.w, gb, h1v.w);
            }
            float h0a[4] = {fmaxf(h0.x, 0.f), fmaxf(h0.y, 0.f), fmaxf(h0.z, 0.f), fmaxf(h0.w, 0.f)};
            float h1a[4] = {fmaxf(h1v.x, 0.f), fmaxf(h1v.y, 0.f), fmaxf(h1v.z, 0.f), fmaxf(h1v.w, 0.f)};

            float4 a0 = make_float4(0.f, 0.f, 0.f, 0.f);
            float4 a1 = make_float4(0.f, 0.f, 0.f, 0.f);
#pragma unroll
            for (int c = 0; c < 4; ++c) {
#pragma unroll 8
                for (int oc = 0; oc < 32; ++oc) {
                    int o = c * 32 + oc;
                    float4 w4 = W2i[o * 32 + lane];
                    float v0 = __shfl_sync(FULLMASK, h0a[c], oc);
                    float v1 = __shfl_sync(FULLMASK, h1a[c], oc);
                    a0.x = fmaf(w4.x, v0, a0.x);  a1.x = fmaf(w4.x, v1, a1.x);
                    a0.y = fmaf(w4.y, v0, a0.y);  a1.y = fmaf(w4.y, v1, a1.y);
                    a0.z = fmaf(w4.z, v0, a0.z);  a1.z = fmaf(w4.z, v1, a1.z);
                    a0.w = fmaf(w4.w, v0, a0.w);  a1.w = fmaf(w4.w, v1, a1.w);
                }
            }
            m.x = fmaxf(m.x, fmaxf(a0.x, a1.x));
            m.y = fmaxf(m.y, fmaxf(a0.y, a1.y));
            m.z = fmaxf(m.z, fmaxf(a0.z, a1.z));
            m.w = fmaxf(m.w, fmaxf(a0.w, a1.w));
        }
        red[w * 128 + lane]      = m.x;
        red[w * 128 + lane + 32] = m.y;
        red[w * 128 + lane + 64] = m.z;
        red[w * 128 + lane + 96] = m.w;
        __syncthreads();
        if (tid < 128) {
            float v = red[tid];
#pragma unroll
            for (int ww = 1; ww < 8; ++ww) v = fmaxf(v, red[ww * 128 + tid]);
            feat[((size_t)b * OUTc + tid) * Sc + s] = v + b2[tid];
        }
    }
}

// ---------------------------------------------------------------------------
extern "C" void kernel_launch(void* const* d_in, const int* in_sizes, int n_in,
                              void* d_out, int out_size) {
    const float* x    = (const float*)d_in[0];
    const int*   sidx = (const int*)d_in[1];
    const float* W1   = (const float*)d_in[2];
    const float* b1   = (const float*)d_in[3];
    const float* W2   = (const float*)d_in[4];
    const float* b2   = (const float*)d_in[5];
    float* out  = (float*)d_out;
    float* feat = out;                                  // [B, OUT, S]
    float* samp = out + (size_t)Bc * OUTc * Sc;         // [B, F, S]

    xsq_kernel<<<(Bc * Nc) / 256, 256>>>(x);
    sampled_kernel<<<(Bc * Fc * Sc) / 256, 256>>>(x, sidx, samp);
    knn_kernel<<<(Bc * Sc) / 32, 256>>>(x, sidx);

    cudaFuncSetAttribute(mlp_kernel, cudaFuncAttributeMaxDynamicSharedMemorySize, SMEM_MLP);
    mlp_kernel<<<304, 256, SMEM_MLP>>>(x, W1, b1, W2, b2, feat);
}

// round 2
// speedup vs baseline: 1.0801x; 1.0801x over previous
#include <cuda_runtime.h>
#include <cuda_bf16.h>
#include <cstdint>

#define FULLMASK 0xffffffffu
#define EMPTYV 3.402823466e38f

constexpr int Bc = 8, Nc = 16384, Fc = 32, Sc = 2048, Kc = 32, OUTc = 128;

// Scratch (device globals: allocation-free)
__device__ float g_xsq[Bc * Nc];
__device__ int   g_knn[Bc * Sc * Kc];

// ---------------------------------------------------------------------------
// Packed fp32x2 helpers (Blackwell FFMA2 path)
// ---------------------------------------------------------------------------
__device__ __forceinline__ unsigned long long splat2(float v) {
    unsigned long long r;
    asm("mov.b64 %0, {%1, %1};" : "=l"(r) : "r"(__float_as_uint(v)));
    return r;
}
__device__ __forceinline__ void fma2(unsigned long long& d,
                                     unsigned long long a,
                                     unsigned long long b) {
    asm("fma.rn.f32x2 %0, %1, %2, %0;" : "+l"(d) : "l"(a), "l"(b));
}
__device__ __forceinline__ float2 unpack2(unsigned long long v) {
    unsigned int lo, hi;
    asm("mov.b64 {%0, %1}, %2;" : "=r"(lo), "=r"(hi) : "l"(v));
    return make_float2(__uint_as_float(lo), __uint_as_float(hi));
}

// ---------------------------------------------------------------------------
// Kernel 1: x_sq[b][n] = sum_f x^2
// ---------------------------------------------------------------------------
__global__ void xsq_kernel(const float* __restrict__ x) {
    int i = blockIdx.x * blockDim.x + threadIdx.x;
    if (i >= Bc * Nc) return;
    const float4* p = (const float4*)(x + (size_t)i * Fc);
    float s = 0.f;
#pragma unroll
    for (int c = 0; c < 8; ++c) {
        float4 v = p[c];
        s += v.x * v.x + v.y * v.y + v.z * v.z + v.w * v.w;
    }
    g_xsq[i] = s;
}

// ---------------------------------------------------------------------------
// Kernel 2: sampled_batch output [B, F, S]
// ---------------------------------------------------------------------------
__global__ void sampled_kernel(const float* __restrict__ x,
                               const int* __restrict__ sidx,
                               float* __restrict__ out2) {
    int i = blockIdx.x * blockDim.x + threadIdx.x;
    if (i >= Bc * Fc * Sc) return;
    int b = i / (Fc * Sc);
    int r = i - b * Fc * Sc;
    int f = r / Sc;
    int s = r - f * Sc;
    int row = sidx[b * Sc + s];
    out2[i] = x[((size_t)(b * Nc + row)) * Fc + f];
}

// ---------------------------------------------------------------------------
// Warp-level bitonic helpers for top-32 maintenance
// ---------------------------------------------------------------------------
__device__ __forceinline__ void cmpSwap(float& d, int& i, int j, bool dirAsc, int lane) {
    float od = __shfl_xor_sync(FULLMASK, d, j);
    int   oi = __shfl_xor_sync(FULLMASK, i, j);
    bool lower = ((lane & j) == 0);
    bool less = (d < od) || (d == od && i < oi);
    bool keep = dirAsc ? (lower == less) : (lower != less);
    if (!keep) { d = od; i = oi; }
}

__device__ __forceinline__ void sortDesc32(float& d, int& i, int lane) {
#pragma unroll
    for (int k = 2; k <= 32; k <<= 1) {
#pragma unroll
        for (int j = k >> 1; j > 0; j >>= 1) {
            bool asc = ((lane & k) == 0);
            cmpSwap(d, i, j, !asc, lane);
        }
    }
}

__device__ __forceinline__ void mergeTop(float& cd, int& ci, float& bd, int& bi, int lane) {
    sortDesc32(bd, bi, lane);
    bool takeNew = (bd < cd) || (bd == cd && bi < ci);
    float nd = takeNew ? bd : cd;
    int   ni = takeNew ? bi : ci;
#pragma unroll
    for (int j = 16; j > 0; j >>= 1) cmpSwap(nd, ni, j, true, lane);
    cd = nd; ci = ni;
    bd = EMPTYV; bi = 0;
}

// ---------------------------------------------------------------------------
// Kernel 3: fused distance + top-K.
// Block: 256 thr, 8 warps, 8 queries/warp -> 64 queries/block, 256 blocks.
// Queries live transposed in smem, read as uniform (broadcast) LDS.128 pairs;
// inner product done in packed fp32x2 (FFMA2), pairs over query dim.
// ---------------------------------------------------------------------------
constexpr int QSTRIDE = 68;   // padded row stride (floats) for qt2

__global__ __launch_bounds__(256, 2) void knn_kernel(const float* __restrict__ x,
                                                     const int* __restrict__ sidx) {
    __shared__ float q_s[64][32];
    __shared__ float qt2[32 * QSTRIDE];  // [f][q] transposed, padded
    __shared__ float sq_s[64];
    __shared__ float xb[128 * 32];       // SW128-swizzled candidate tile
    __shared__ float xsq_s[128];

    int b = blockIdx.x >> 5;                 // 32 blocks per batch
    int qbase = (blockIdx.x & 31) * 64;
    int tid = threadIdx.x, lane = tid & 31, w = tid >> 5;
    int wq = w * 8;

    // gather 64 query points (float4 granularity)
#pragma unroll
    for (int it = 0; it < 2; ++it) {
        int idx = tid + it * 256;
        int q = idx >> 3, p = idx & 7;
        int row = sidx[b * Sc + qbase + q];
        float4 v = *(const float4*)(x + ((size_t)(b * Nc + row)) * Fc + p * 4);
        *(float4*)&q_s[q][p * 4] = v;
    }
    __syncthreads();
    if (tid < 64) {
        float s = 0.f;
#pragma unroll
        for (int f = 0; f < 32; ++f) { float v = q_s[tid][f]; s += v * v; }
        sq_s[tid] = s;
    }
    // transpose queries: qt2[f][q]
#pragma unroll
    for (int it = 0; it < 8; ++it) {
        int idx = tid + it * 256;
        int q = idx >> 5, f = idx & 31;
        qt2[f * QSTRIDE + q] = q_s[q][f];
    }
    __syncthreads();

    float sq[8];
#pragma unroll
    for (int qi = 0; qi < 8; ++qi) sq[qi] = sq_s[wq + qi];

    float cur_d[8], buf_d[8];
    int   cur_i[8], buf_i[8];
#pragma unroll
    for (int qi = 0; qi < 8; ++qi) {
        cur_d[qi] = EMPTYV; cur_i[qi] = 0;
        buf_d[qi] = EMPTYV; buf_i[qi] = 0;
    }

    for (int n0 = 0; n0 < Nc; n0 += 128) {
        __syncthreads();
#pragma unroll
        for (int it = 0; it < 4; ++it) {
            int t = tid + it * 256;
            int r = t >> 3, p = t & 7;
            float4 v = *(const float4*)(x + ((size_t)(b * Nc + n0 + r)) * Fc + p * 4);
            int off = r * 128 + p * 16;
            off ^= (off >> 3) & 0x70;
            *(float4*)((char*)xb + off) = v;
        }
        if (tid < 128) xsq_s[tid] = g_xsq[b * Nc + n0 + tid];
        __syncthreads();

        // packed accumulators: acc2[m][sub] covers queries {wq+2m, wq+2m+1},
        // candidate c = sub*32+lane
        unsigned long long acc2[4][4];
#pragma unroll
        for (int m = 0; m < 4; ++m)
#pragma unroll
            for (int s2 = 0; s2 < 4; ++s2) acc2[m][s2] = 0ULL;

#pragma unroll
        for (int p = 0; p < 8; ++p) {
            // uniform loads: query pairs for f = 4p..4p+3
            unsigned long long qp[4][4];
#pragma unroll
            for (int j = 0; j < 4; ++j) {
                ulonglong2 qa = *(const ulonglong2*)&qt2[(4 * p + j) * QSTRIDE + wq];
                ulonglong2 qb = *(const ulonglong2*)&qt2[(4 * p + j) * QSTRIDE + wq + 4];
                qp[j][0] = qa.x; qp[j][1] = qa.y;
                qp[j][2] = qb.x; qp[j][3] = qb.y;
            }
#pragma unroll
            for (int s2 = 0; s2 < 4; ++s2) {
                int c = s2 * 32 + lane;
                int off = c * 128 + p * 16;
                off ^= (off >> 3) & 0x70;
                float4 xv = *(const float4*)((const char*)xb + off);
                const float xe[4] = {xv.x, xv.y, xv.z, xv.w};
#pragma unroll
                for (int j = 0; j < 4; ++j) {
                    unsigned long long xs = splat2(xe[j]);
#pragma unroll
                    for (int m = 0; m < 4; ++m) fma2(acc2[m][s2], qp[j][m], xs);
                }
            }
        }

        // distances + selection
        float xq[4];
        int gi[4];
#pragma unroll
        for (int s2 = 0; s2 < 4; ++s2) {
            xq[s2] = xsq_s[s2 * 32 + lane];
            gi[s2] = n0 + s2 * 32 + lane;
        }
#pragma unroll
        for (int qi = 0; qi < 8; ++qi) {
            float thr = __shfl_sync(FULLMASK, cur_d[qi], 31);
#pragma unroll
            for (int s2 = 0; s2 < 4; ++s2) {
                float2 av = unpack2(acc2[qi >> 1][s2]);
                float a = (qi & 1) ? av.y : av.x;
                float d = sq[qi] + xq[s2] - 2.f * a;
                bool beat = d < thr;
                bool occ = buf_d[qi] < EMPTYV;
                if (__ballot_sync(FULLMASK, beat && occ)) {
                    mergeTop(cur_d[qi], cur_i[qi], buf_d[qi], buf_i[qi], lane);
                    thr = __shfl_sync(FULLMASK, cur_d[qi], 31);
                    beat = d < thr;
                }
                if (beat) { buf_d[qi] = d; buf_i[qi] = gi[s2]; }
            }
        }
    }

#pragma unroll
    for (int qi = 0; qi < 8; ++qi) {
        bool occ = buf_d[qi] < EMPTYV;
        if (__ballot_sync(FULLMASK, occ))
            mergeTop(cur_d[qi], cur_i[qi], buf_d[qi], buf_i[qi], lane);
        g_knn[(b * Sc + qbase + wq + qi) * Kc + lane] = cur_i[qi];
    }
}

// ---------------------------------------------------------------------------
// Kernel 4: gather neighbors, 2-layer pointwise MLP, max-pool over K.
// 512 threads = 16 warps; warps 0-7 -> query A, warps 8-15 -> query B.
// Each warp: 4 neighbors of its query. Layer math in packed fp32x2, pairs
// over the neighbor dim; h round-trips through a warp-private smem patch
// (uniform LDS.128 broadcast) -> zero shuffles.
// ---------------------------------------------------------------------------
constexpr int GT_STRIDE = 36;  // padded row stride (floats) for gt
constexpr int SMEM_MLP = (1024 + 4096 + 32) * (int)sizeof(float4)
                       + (2 * 32 * GT_STRIDE + 16 * 512 + 2048) * (int)sizeof(float);

__global__ __launch_bounds__(512, 1) void mlp_kernel(const float* __restrict__ x,
                                                     const float* __restrict__ W1,
                                                     const float* __restrict__ b1,
                                                     const float* __restrict__ W2,
                                                     const float* __restrict__ b2,
                                                     float* __restrict__ feat) {
    extern __shared__ char smem_raw[];
    float4* W1i = (float4*)smem_raw;            // [f][lane] -> chans l,l+32,l+64,l+96
    float4* W2i = W1i + 1024;                   // [o][lane]
    float4* b1i = W2i + 4096;                   // [lane]
    float*  gt  = (float*)(b1i + 32);           // [2 queries][f][k] padded
    float*  hsm = gt + 2 * 32 * GT_STRIDE;      // [16 warps][o=128][k=4]
    float*  red = hsm + 16 * 512;               // [2 queries][8 wg][128]

    int tid = threadIdx.x, lane = tid & 31, w = tid >> 5;
    int qsel = w >> 3, wg = w & 7, wk = wg * 4;

    for (int t = tid; t < 4096; t += 512) {
        int f = t >> 7, l = (t >> 2) & 31, j = t & 3;
        ((float*)&W1i[f * 32 + l])[j] = W1[(l + 32 * j) * Fc + f];
    }
    for (int t = tid; t < 16384; t += 512) {
        int o = t >> 7, l = (t >> 2) & 31, j = t & 3;
        ((float*)&W2i[o * 32 + l])[j] = W2[(l + 32 * j) * OUTc + o];
    }
    if (tid < 32)
        b1i[tid] = make_float4(b1[tid], b1[tid + 32], b1[tid + 64], b1[tid + 96]);

    for (int qp_ = blockIdx.x; qp_ < (Bc * Sc) / 2; qp_ += gridDim.x) {
        __syncthreads();   // weights visible (1st iter) + gt/red reuse
        // gather 2 queries x 32 neighbors, write transposed into gt
        {
            int q2 = tid >> 8, k = (tid >> 3) & 31, p = tid & 7;
            int qg = qp_ * 2 + q2;
            int bq = qg >> 11;
            int row = g_knn[qg * Kc + k];
            float4 v = *(const float4*)(x + ((size_t)(bq * Nc + row)) * Fc + p * 4);
            float* g = gt + q2 * 32 * GT_STRIDE;
            g[(4 * p + 0) * GT_STRIDE + k] = v.x;
            g[(4 * p + 1) * GT_STRIDE + k] = v.y;
            g[(4 * p + 2) * GT_STRIDE + k] = v.z;
            g[(4 * p + 3) * GT_STRIDE + k] = v.w;
        }
        __syncthreads();

        // ---- layer 1: h[k][o] = relu(sum_f W1[o][f] g[k][f] + b1[o]) ----
        unsigned long long h2[4][2];
        {
            float4 bb = b1i[lane];
            const float be[4] = {bb.x, bb.y, bb.z, bb.w};
#pragma unroll
            for (int c = 0; c < 4; ++c) {
                unsigned long long bs = splat2(be[c]);
                h2[c][0] = bs; h2[c][1] = bs;
            }
            const float* g = gt + qsel * 32 * GT_STRIDE;
#pragma unroll
            for (int f = 0; f < 32; ++f) {
                ulonglong2 gp = *(const ulonglong2*)&g[f * GT_STRIDE + wk];
                float4 w1 = W1i[f * 32 + lane];
                const float we[4] = {w1.x, w1.y, w1.z, w1.w};
#pragma unroll
                for (int c = 0; c < 4; ++c) {
                    unsigned long long ws = splat2(we[c]);
                    fma2(h2[c][0], ws, gp.x);
                    fma2(h2[c][1], ws, gp.y);
                }
            }
        }
        // relu + deposit into warp-private hsm patch [o][k]
        float* hw = hsm + w * 512;
#pragma unroll
        for (int c = 0; c < 4; ++c) {
            float2 p0 = unpack2(h2[c][0]);
            float2 p1 = unpack2(h2[c][1]);
            float4 hv = make_float4(fmaxf(p0.x, 0.f), fmaxf(p0.y, 0.f),
                                    fmaxf(p1.x, 0.f), fmaxf(p1.y, 0.f));
            *(float4*)&hw[(lane + 32 * c) * 4] = hv;
        }
        __syncwarp();

        // ---- layer 2: y[k][p] = sum_o W2[p][o] h[k][o]; max over k ----
        unsigned long long y2[4][2];
#pragma unroll
        for (int c = 0; c < 4; ++c) { y2[c][0] = 0ULL; y2[c][1] = 0ULL; }
#pragma unroll 4
        for (int o = 0; o < 128; ++o) {
            ulonglong2 hp = *(const ulonglong2*)&hw[o * 4];   // uniform broadcast
            float4 w2 = W2i[o * 32 + lane];
            const float we[4] = {w2.x, w2.y, w2.z, w2.w};
#pragma unroll
            for (int c = 0; c < 4; ++c) {
                unsigned long long ws = splat2(we[c]);
                fma2(y2[c][0], ws, hp.x);
                fma2(y2[c][1], ws, hp.y);
            }
        }
#pragma unroll
        for (int c = 0; c < 4; ++c) {
            float2 a0 = unpack2(y2[c][0]);
            float2 a1 = unpack2(y2[c][1]);
            float m = fmaxf(fmaxf(a0.x, a0.y), fmaxf(a1.x, a1.y));
            red[qsel * 1024 + wg * 128 + lane + 32 * c] = m;
        }
        __syncthreads();

        if (tid < 256) {
            int qs = tid >> 7, o = tid & 127;
            float v = red[qs * 1024 + o];
#pragma unroll
            for (int ww = 1; ww < 8; ++ww) v = fmaxf(v, red[qs * 1024 + ww * 128 + o]);
            int qg = qp_ * 2 + qs;
            int bq = qg >> 11, s = qg & 2047;
            feat[((size_t)bq * OUTc + o) * Sc + s] = v + b2[o];
        }
    }
}

// ---------------------------------------------------------------------------
extern "C" void kernel_launch(void* const* d_in, const int* in_sizes, int n_in,
                              void* d_out, int out_size) {
    const float* x    = (const float*)d_in[0];
    const int*   sidx = (const int*)d_in[1];
    const float* W1   = (const float*)d_in[2];
    const float* b1   = (const float*)d_in[3];
    const float* W2   = (const float*)d_in[4];
    const float* b2   = (const float*)d_in[5];
    float* out  = (float*)d_out;
    float* feat = out;                                  // [B, OUT, S]
    float* samp = out + (size_t)Bc * OUTc * Sc;         // [B, F, S]

    xsq_kernel<<<(Bc * Nc) / 256, 256>>>(x);
    sampled_kernel<<<(Bc * Fc * Sc) / 256, 256>>>(x, sidx, samp);
    knn_kernel<<<(Bc * Sc) / 64, 256>>>(x, sidx);

    cudaFuncSetAttribute(mlp_kernel, cudaFuncAttributeMaxDynamicSharedMemorySize, SMEM_MLP);
    mlp_kernel<<<148, 512, SMEM_MLP>>>(x, W1, b1, W2, b2, feat);
}

// round 4
// speedup vs baseline: 1.8895x; 1.7493x over previous
#include <cuda_runtime.h>
#include <cuda_bf16.h>
#include <cstdint>

#define FULLMASK 0xffffffffu
#define EMPTYV 3.402823466e38f

constexpr int Bc = 8, Nc = 16384, Fc = 32, Sc = 2048, Kc = 32, OUTc = 128;

// Scratch (device globals: allocation-free)
__device__ float g_xsq[Bc * Nc];
__device__ int   g_knn[Bc * Sc * Kc];

// ---------------------------------------------------------------------------
// Packed fp32x2 helpers (Blackwell FFMA2 path)
// ---------------------------------------------------------------------------
__device__ __forceinline__ unsigned long long splat2(float v) {
    unsigned long long r;
    asm("mov.b64 %0, {%1, %1};" : "=l"(r) : "r"(__float_as_uint(v)));
    return r;
}
__device__ __forceinline__ void fma2(unsigned long long& d,
                                     unsigned long long a,
                                     unsigned long long b) {
    asm("fma.rn.f32x2 %0, %1, %2, %0;" : "+l"(d) : "l"(a), "l"(b));
}
__device__ __forceinline__ float2 unpack2(unsigned long long v) {
    unsigned int lo, hi;
    asm("mov.b64 {%0, %1}, %2;" : "=r"(lo), "=r"(hi) : "l"(v));
    return make_float2(__uint_as_float(lo), __uint_as_float(hi));
}

// ---------------------------------------------------------------------------
// Kernel 1: x_sq[b][n] = sum_f x^2
// ---------------------------------------------------------------------------
__global__ void xsq_kernel(const float* __restrict__ x) {
    int i = blockIdx.x * blockDim.x + threadIdx.x;
    if (i >= Bc * Nc) return;
    const float4* p = (const float4*)(x + (size_t)i * Fc);
    float s = 0.f;
#pragma unroll
    for (int c = 0; c < 8; ++c) {
        float4 v = p[c];
        s += v.x * v.x + v.y * v.y + v.z * v.z + v.w * v.w;
    }
    g_xsq[i] = s;
}

// ---------------------------------------------------------------------------
// Kernel 2: sampled_batch output [B, F, S]
// ---------------------------------------------------------------------------
__global__ void sampled_kernel(const float* __restrict__ x,
                               const int* __restrict__ sidx,
                               float* __restrict__ out2) {
    int i = blockIdx.x * blockDim.x + threadIdx.x;
    if (i >= Bc * Fc * Sc) return;
    int b = i / (Fc * Sc);
    int r = i - b * Fc * Sc;
    int f = r / Sc;
    int s = r - f * Sc;
    int row = sidx[b * Sc + s];
    out2[i] = x[((size_t)(b * Nc + row)) * Fc + f];
}

// ---------------------------------------------------------------------------
// Warp-level bitonic helpers for top-32 maintenance
// ---------------------------------------------------------------------------
__device__ __forceinline__ void cmpSwap(float& d, int& i, int j, bool dirAsc, int lane) {
    float od = __shfl_xor_sync(FULLMASK, d, j);
    int   oi = __shfl_xor_sync(FULLMASK, i, j);
    bool lower = ((lane & j) == 0);
    bool less = (d < od) || (d == od && i < oi);
    bool keep = dirAsc ? (lower == less) : (lower != less);
    if (!keep) { d = od; i = oi; }
}

__device__ __forceinline__ void sortDesc32(float& d, int& i, int lane) {
#pragma unroll
    for (int k = 2; k <= 32; k <<= 1) {
#pragma unroll
        for (int j = k >> 1; j > 0; j >>= 1) {
            bool asc = ((lane & k) == 0);
            cmpSwap(d, i, j, !asc, lane);
        }
    }
}

__device__ __forceinline__ void mergeTop(float& cd, int& ci, float& bd, int& bi, int lane) {
    sortDesc32(bd, bi, lane);
    bool takeNew = (bd < cd) || (bd == cd && bi < ci);
    float nd = takeNew ? bd : cd;
    int   ni = takeNew ? bi : ci;
#pragma unroll
    for (int j = 16; j > 0; j >>= 1) cmpSwap(nd, ni, j, true, lane);
    cd = nd; ci = ni;
}

// ---------------------------------------------------------------------------
// Kernel 3: fused distance + top-K, threshold + overflow-list selection.
// Block: 256 thr, 8 warps, 8 queries/warp -> 64 queries/block, 256 blocks.
// ---------------------------------------------------------------------------
constexpr int QSTRIDE = 68;   // padded row stride (floats) for qt2
constexpr int CAPk = 96;      // overflow-list capacity per query

struct KnnSmem {
    float q_s[64][32];                  // raw queries
    float qt2[32 * QSTRIDE];            // [f][q] transposed, padded
    float sq_s[64];
    float xb[128 * 32];                 // SW128-swizzled candidate tile
    float xsq_s[128];
    float curD[8][8][32];               // running top-32 per (warp, query)
    int   curI[8][8][32];
    unsigned long long list[8][8][CAPk];
    int   cnt[8][8];
    float thr[8][8];
};
constexpr int SMEM_KNN = (int)sizeof(KnnSmem);

__device__ __forceinline__ void reselect(KnnSmem* sm, int w, int qi, int lane) {
    float cd = sm->curD[w][qi][lane];
    int   ci = sm->curI[w][qi][lane];
    int n = sm->cnt[w][qi];
    for (int base = 0; base < n; base += 32) {
        float bd = EMPTYV; int bi = 0x7fffffff;
        if (base + lane < n) {
            unsigned long long e = sm->list[w][qi][base + lane];
            bd = __uint_as_float((unsigned)e);
            bi = (int)(unsigned)(e >> 32);
        }
        mergeTop(cd, ci, bd, bi, lane);
    }
    sm->curD[w][qi][lane] = cd;
    sm->curI[w][qi][lane] = ci;
    sm->cnt[w][qi] = 0;
    sm->thr[w][qi] = __shfl_sync(FULLMASK, cd, 31);
}

__global__ __launch_bounds__(256) void knn_kernel(const float* __restrict__ x,
                                                  const int* __restrict__ sidx) {
    extern __shared__ char smem_raw[];
    KnnSmem* sm = (KnnSmem*)smem_raw;

    int b = blockIdx.x >> 5;                 // 32 blocks per batch
    int qbase = (blockIdx.x & 31) * 64;
    int tid = threadIdx.x, lane = tid & 31, w = tid >> 5;
    int wq = w * 8;

    // init selection state
    if (tid < 64) {
        sm->cnt[tid >> 3][tid & 7] = 0;
        sm->thr[tid >> 3][tid & 7] = EMPTYV;
    }
    for (int t = tid; t < 8 * 8 * 32; t += 256) {
        ((float*)sm->curD)[t] = EMPTYV;
        ((int*)sm->curI)[t] = 0;
    }

    // gather 64 query points
#pragma unroll
    for (int it = 0; it < 2; ++it) {
        int idx = tid + it * 256;
        int q = idx >> 3, p = idx & 7;
        int row = sidx[b * Sc + qbase + q];
        float4 v = *(const float4*)(x + ((size_t)(b * Nc + row)) * Fc + p * 4);
        *(float4*)&sm->q_s[q][p * 4] = v;
    }
    __syncthreads();
    if (tid < 64) {
        float s = 0.f;
#pragma unroll
        for (int f = 0; f < 32; ++f) { float v = sm->q_s[tid][f]; s += v * v; }
        sm->sq_s[tid] = s;
    }
#pragma unroll
    for (int it = 0; it < 8; ++it) {
        int idx = tid + it * 256;
        int q = idx >> 5, f = idx & 31;
        sm->qt2[f * QSTRIDE + q] = sm->q_s[q][f];
    }
    __syncthreads();

    float sqv[8];
#pragma unroll
    for (int qi = 0; qi < 8; ++qi) sqv[qi] = sm->sq_s[wq + qi];

    for (int n0 = 0; n0 < Nc; n0 += 128) {
        __syncthreads();
#pragma unroll
        for (int it = 0; it < 4; ++it) {
            int t = tid + it * 256;
            int r = t >> 3, p = t & 7;
            float4 v = *(const float4*)(x + ((size_t)(b * Nc + n0 + r)) * Fc + p * 4);
            int off = r * 128 + p * 16;
            off ^= (off >> 3) & 0x70;
            *(float4*)((char*)sm->xb + off) = v;
        }
        if (tid < 128) sm->xsq_s[tid] = g_xsq[b * Nc + n0 + tid];
        __syncthreads();

        // ---- dot products: acc2[m][sub] = pair {wq+2m, wq+2m+1} x cand sub*32+lane
        unsigned long long acc2[4][4];
#pragma unroll
        for (int m = 0; m < 4; ++m)
#pragma unroll
            for (int s2 = 0; s2 < 4; ++s2) acc2[m][s2] = 0ULL;

#pragma unroll
        for (int p = 0; p < 8; ++p) {
            unsigned long long qp[4][4];
#pragma unroll
            for (int j = 0; j < 4; ++j) {
                ulonglong2 qa = *(const ulonglong2*)&sm->qt2[(4 * p + j) * QSTRIDE + wq];
                ulonglong2 qb = *(const ulonglong2*)&sm->qt2[(4 * p + j) * QSTRIDE + wq + 4];
                qp[j][0] = qa.x; qp[j][1] = qa.y;
                qp[j][2] = qb.x; qp[j][3] = qb.y;
            }
#pragma unroll
            for (int s2 = 0; s2 < 4; ++s2) {
                int c = s2 * 32 + lane;
                int off = c * 128 + p * 16;
                off ^= (off >> 3) & 0x70;
                float4 xv = *(const float4*)((const char*)sm->xb + off);
                const float xe[4] = {xv.x, xv.y, xv.z, xv.w};
#pragma unroll
                for (int j = 0; j < 4; ++j) {
                    unsigned long long xs = splat2(xe[j]);
#pragma unroll
                    for (int m = 0; m < 4; ++m) fma2(acc2[m][s2], qp[j][m], xs);
                }
            }
        }

        float xq[4];
#pragma unroll
        for (int s2 = 0; s2 < 4; ++s2) xq[s2] = sm->xsq_s[s2 * 32 + lane];

        // ---- selection: threshold test + overflow-list push; two halves
#pragma unroll
        for (int half = 0; half < 2; ++half) {
            float tr[8];
#pragma unroll
            for (int qi = 0; qi < 8; ++qi) tr[qi] = sm->thr[w][qi];
#pragma unroll
            for (int qi = 0; qi < 8; ++qi) {
#pragma unroll
                for (int s2h = 0; s2h < 2; ++s2h) {
                    int s2 = half * 2 + s2h;
                    float2 av = unpack2(acc2[qi >> 1][s2]);
                    float a = (qi & 1) ? av.y : av.x;
                    float d = sqv[qi] + xq[s2] - 2.f * a;
                    bool beat = d < tr[qi];
                    unsigned bm = __ballot_sync(FULLMASK, beat);
                    if (bm) {
                        int c0 = sm->cnt[w][qi];
                        if (beat) {
                            int rank = __popc(bm & ((1u << lane) - 1));
                            unsigned long long e =
                                ((unsigned long long)(unsigned)(n0 + s2 * 32 + lane) << 32)
                              | (unsigned long long)__float_as_uint(d);
                            sm->list[w][qi][c0 + rank] = e;
                        }
                        sm->cnt[w][qi] = c0 + __popc(bm);
                    }
                }
            }
            // checkpoint: flush any list at >=32 (bounds growth; single merge site)
#pragma unroll 1
            for (int qi = 0; qi < 8; ++qi) {
                if (sm->cnt[w][qi] >= 32) reselect(sm, w, qi, lane);
            }
        }
    }

    // final flush + write neighbor indices
#pragma unroll 1
    for (int qi = 0; qi < 8; ++qi) {
        if (sm->cnt[w][qi] > 0) reselect(sm, w, qi, lane);
        g_knn[(b * Sc + qbase + wq + qi) * Kc + lane] = sm->curI[w][qi][lane];
    }
}

// ---------------------------------------------------------------------------
// Kernel 4: gather neighbors, 2-layer pointwise MLP, max-pool over K.
// 512 threads = 16 warps; 4 queries/block; warp w -> query w>>2,
// neighbors (w&3)*8 .. +7.  All math packed fp32x2; h round-trips through a
// warp-private smem patch read back as uniform LDS.128 -> zero shuffles.
// ---------------------------------------------------------------------------
constexpr int GT_STRIDE = 36;
struct MlpSmem {
    float4 W1i[32 * 32];     // [f][lane] -> chans l, l+32, l+64, l+96
    float4 W2i[128 * 32];    // [o][lane]
    float4 b1i[32];
    float  gt[4][32][GT_STRIDE];   // [query][f][k]
    float  hsm[16][128 * 8];       // per warp: [o][k(8)]
    float  red[4][4][128];         // [query][warp-in-query][chan]
};
constexpr int SMEM_MLP = (int)sizeof(MlpSmem);

__global__ __launch_bounds__(512) void mlp_kernel(const float* __restrict__ x,
                                                  const float* __restrict__ W1,
                                                  const float* __restrict__ b1,
                                                  const float* __restrict__ W2,
                                                  const float* __restrict__ b2,
                                                  float* __restrict__ feat) {
    extern __shared__ char smem_raw[];
    MlpSmem* sm = (MlpSmem*)smem_raw;

    int tid = threadIdx.x, lane = tid & 31, w = tid >> 5;
    int q = w >> 2, kb = (w & 3) * 8;

    for (int t = tid; t < 4096; t += 512) {
        int f = t >> 7, l = (t >> 2) & 31, j = t & 3;
        ((float*)&sm->W1i[f * 32 + l])[j] = W1[(l + 32 * j) * Fc + f];
    }
    for (int t = tid; t < 16384; t += 512) {
        int o = t >> 7, l = (t >> 2) & 31, j = t & 3;
        ((float*)&sm->W2i[o * 32 + l])[j] = W2[(l + 32 * j) * OUTc + o];
    }
    if (tid < 32)
        sm->b1i[tid] = make_float4(b1[tid], b1[tid + 32], b1[tid + 64], b1[tid + 96]);

    for (int grp = blockIdx.x; grp < (Bc * Sc) / 4; grp += gridDim.x) {
        __syncthreads();   // weights visible (1st iter) + gt/hsm/red reuse
        // gather 4 queries x 32 neighbors each -> transposed gt
#pragma unroll
        for (int it = 0; it < 2; ++it) {
            int idx = tid + it * 512;
            int q2 = idx >> 8, k = (idx >> 3) & 31, p = idx & 7;
            int qg = grp * 4 + q2;
            int bq = qg >> 11;
            int row = g_knn[qg * Kc + k];
            float4 v = *(const float4*)(x + ((size_t)(bq * Nc + row)) * Fc + p * 4);
            sm->gt[q2][4 * p + 0][k] = v.x;
            sm->gt[q2][4 * p + 1][k] = v.y;
            sm->gt[q2][4 * p + 2][k] = v.z;
            sm->gt[q2][4 * p + 3][k] = v.w;
        }
        __syncthreads();

        // ---- layer 1: h[k][o] = relu(sum_f W1[o][f] g[k][f] + b1[o])
        unsigned long long h2[4][4];   // [chan c][k-pair j]
        {
            float4 bb = sm->b1i[lane];
            const float be[4] = {bb.x, bb.y, bb.z, bb.w};
#pragma unroll
            for (int c = 0; c < 4; ++c) {
                unsigned long long bs = splat2(be[c]);
#pragma unroll
                for (int j = 0; j < 4; ++j) h2[c][j] = bs;
            }
#pragma unroll
            for (int f = 0; f < 32; ++f) {
                ulonglong2 g0 = *(const ulonglong2*)&sm->gt[q][f][kb];
                ulonglong2 g1 = *(const ulonglong2*)&sm->gt[q][f][kb + 4];
                float4 w1 = sm->W1i[f * 32 + lane];
                const float we[4] = {w1.x, w1.y, w1.z, w1.w};
#pragma unroll
                for (int c = 0; c < 4; ++c) {
                    unsigned long long ws = splat2(we[c]);
                    fma2(h2[c][0], ws, g0.x);
                    fma2(h2[c][1], ws, g0.y);
                    fma2(h2[c][2], ws, g1.x);
                    fma2(h2[c][3], ws, g1.y);
                }
            }
        }
        // relu + deposit into warp-private hsm patch [o][k 8]
        float* hw = sm->hsm[w];
#pragma unroll
        for (int c = 0; c < 4; ++c) {
            float2 p0 = unpack2(h2[c][0]);
            float2 p1 = unpack2(h2[c][1]);
            float2 p2 = unpack2(h2[c][2]);
            float2 p3 = unpack2(h2[c][3]);
            float4 va = make_float4(fmaxf(p0.x, 0.f), fmaxf(p0.y, 0.f),
                                    fmaxf(p1.x, 0.f), fmaxf(p1.y, 0.f));
            float4 vb = make_float4(fmaxf(p2.x, 0.f), fmaxf(p2.y, 0.f),
                                    fmaxf(p3.x, 0.f), fmaxf(p3.y, 0.f));
            *(float4*)&hw[(lane + 32 * c) * 8]     = va;
            *(float4*)&hw[(lane + 32 * c) * 8 + 4] = vb;
        }
        __syncwarp();

        // ---- layer 2: y[k][p] = sum_o W2[p][o] h[k][o]; max over k
        unsigned long long y2[4][4];
#pragma unroll
        for (int c = 0; c < 4; ++c)
#pragma unroll
            for (int j = 0; j < 4; ++j) y2[c][j] = 0ULL;
#pragma unroll 4
        for (int o = 0; o < 128; ++o) {
            ulonglong2 hp0 = *(const ulonglong2*)&hw[o * 8];       // uniform
            ulonglong2 hp1 = *(const ulonglong2*)&hw[o * 8 + 4];   // uniform
            float4 w2 = sm->W2i[o * 32 + lane];
            const float we[4] = {w2.x, w2.y, w2.z, w2.w};
#pragma unroll
            for (int c = 0; c < 4; ++c) {
                unsigned long long ws = splat2(we[c]);
                fma2(y2[c][0], ws, hp0.x);
                fma2(y2[c][1], ws, hp0.y);
                fma2(y2[c][2], ws, hp1.x);
                fma2(y2[c][3], ws, hp1.y);
            }
        }
#pragma unroll
        for (int c = 0; c < 4; ++c) {
            float2 a0 = unpack2(y2[c][0]);
            float2 a1 = unpack2(y2[c][1]);
            float2 a2 = unpack2(y2[c][2]);
            float2 a3 = unpack2(y2[c][3]);
            float m = fmaxf(fmaxf(fmaxf(a0.x, a0.y), fmaxf(a1.x, a1.y)),
                            fmaxf(fmaxf(a2.x, a2.y), fmaxf(a3.x, a3.y)));
            sm->red[q][w & 3][lane + 32 * c] = m;
        }
        __syncthreads();

        {
            int q2 = tid >> 7, o = tid & 127;
            float v = sm->red[q2][0][o];
#pragma unroll
            for (int ww = 1; ww < 4; ++ww) v = fmaxf(v, sm->red[q2][ww][o]);
            int qg = grp * 4 + q2;
            int bq = qg >> 11, s = qg & 2047;
            feat[((size_t)bq * OUTc + o) * Sc + s] = v + b2[o];
        }
    }
}

// ---------------------------------------------------------------------------
extern "C" void kernel_launch(void* const* d_in, const int* in_sizes, int n_in,
                              void* d_out, int out_size) {
    const float* x    = (const float*)d_in[0];
    const int*   sidx = (const int*)d_in[1];
    const float* W1   = (const float*)d_in[2];
    const float* b1   = (const float*)d_in[3];
    const float* W2   = (const float*)d_in[4];
    const float* b2   = (const float*)d_in[5];
    float* out  = (float*)d_out;
    float* feat = out;                                  // [B, OUT, S]
    float* samp = out + (size_t)Bc * OUTc * Sc;         // [B, F, S]

    xsq_kernel<<<(Bc * Nc) / 256, 256>>>(x);
    sampled_kernel<<<(Bc * Fc * Sc) / 256, 256>>>(x, sidx, samp);

    cudaFuncSetAttribute(knn_kernel, cudaFuncAttributeMaxDynamicSharedMemorySize, SMEM_KNN);
    knn_kernel<<<(Bc * Sc) / 64, 256, SMEM_KNN>>>(x, sidx);

    cudaFuncSetAttribute(mlp_kernel, cudaFuncAttributeMaxDynamicSharedMemorySize, SMEM_MLP);
    mlp_kernel<<<148, 512, SMEM_MLP>>>(x, W1, b1, W2, b2, feat);
}

// round 5
// speedup vs baseline: 3.2426x; 1.7162x over previous
#include <cuda_runtime.h>
#include <cuda_bf16.h>
#include <cstdint>

#define FULLMASK 0xffffffffu
#define EMPTYV 3.402823466e38f

constexpr int Bc = 8, Nc = 16384, Fc = 32, Sc = 2048, Kc = 32, OUTc = 128;

// Scratch (device globals: allocation-free)
__device__ float g_xsq[Bc * Nc];
__device__ int   g_knn[Bc * Sc * Kc];

// ---------------------------------------------------------------------------
// Packed fp32x2 helpers
// ---------------------------------------------------------------------------
__device__ __forceinline__ unsigned long long splat2(float v) {
    unsigned long long r;
    asm("mov.b64 %0, {%1, %1};" : "=l"(r) : "r"(__float_as_uint(v)));
    return r;
}
__device__ __forceinline__ void fma2(unsigned long long& d,
                                     unsigned long long a,
                                     unsigned long long b) {
    asm("fma.rn.f32x2 %0, %1, %2, %0;" : "+l"(d) : "l"(a), "l"(b));
}
__device__ __forceinline__ float2 unpack2(unsigned long long v) {
    unsigned int lo, hi;
    asm("mov.b64 {%0, %1}, %2;" : "=r"(lo), "=r"(hi) : "l"(v));
    return make_float2(__uint_as_float(lo), __uint_as_float(hi));
}

// ---------------------------------------------------------------------------
// Kernel 1: x_sq
// ---------------------------------------------------------------------------
__global__ void xsq_kernel(const float* __restrict__ x) {
    int i = blockIdx.x * blockDim.x + threadIdx.x;
    if (i >= Bc * Nc) return;
    const float4* p = (const float4*)(x + (size_t)i * Fc);
    float s = 0.f;
#pragma unroll
    for (int c = 0; c < 8; ++c) {
        float4 v = p[c];
        s += v.x * v.x + v.y * v.y + v.z * v.z + v.w * v.w;
    }
    g_xsq[i] = s;
}

// ---------------------------------------------------------------------------
// Kernel 2: sampled_batch output [B, F, S]
// ---------------------------------------------------------------------------
__global__ void sampled_kernel(const float* __restrict__ x,
                               const int* __restrict__ sidx,
                               float* __restrict__ out2) {
    int i = blockIdx.x * blockDim.x + threadIdx.x;
    if (i >= Bc * Fc * Sc) return;
    int b = i / (Fc * Sc);
    int r = i - b * Fc * Sc;
    int f = r / Sc;
    int s = r - f * Sc;
    int row = sidx[b * Sc + s];
    out2[i] = x[((size_t)(b * Nc + row)) * Fc + f];
}

// ---------------------------------------------------------------------------
// Warp-level bitonic helpers
// ---------------------------------------------------------------------------
__device__ __forceinline__ void cmpSwap(float& d, int& i, int j, bool dirAsc, int lane) {
    float od = __shfl_xor_sync(FULLMASK, d, j);
    int   oi = __shfl_xor_sync(FULLMASK, i, j);
    bool lower = ((lane & j) == 0);
    bool less = (d < od) || (d == od && i < oi);
    bool keep = dirAsc ? (lower == less) : (lower != less);
    if (!keep) { d = od; i = oi; }
}

__device__ __forceinline__ void sortDesc32(float& d, int& i, int lane) {
#pragma unroll
    for (int k = 2; k <= 32; k <<= 1) {
#pragma unroll
        for (int j = k >> 1; j > 0; j >>= 1) {
            bool asc = ((lane & k) == 0);
            cmpSwap(d, i, j, !asc, lane);
        }
    }
}

__device__ __forceinline__ void mergeTop(float& cd, int& ci, float& bd, int& bi, int lane) {
    sortDesc32(bd, bi, lane);
    bool takeNew = (bd < cd) || (bd == cd && bi < ci);
    float nd = takeNew ? bd : cd;
    int   ni = takeNew ? bi : ci;
#pragma unroll
    for (int j = 16; j > 0; j >>= 1) cmpSwap(nd, ni, j, true, lane);
    cd = nd; ci = ni;
}

// ---------------------------------------------------------------------------
// Kernel 3: fused distance + top-K
// Block: 256 thr, 8 warps, 8 queries/warp, 64 queries/block, 256 blocks.
// ---------------------------------------------------------------------------
constexpr int QSTRIDE = 68;   // padded row stride (floats) for qt2
constexpr int CAPk = 64;      // overflow-list capacity per query

struct KnnSmem {
    float qt2[32 * QSTRIDE];            // [f][q] transposed, padded
    float sq_s[64];
    float xb[2][128 * 32];              // double-buffered swizzled tiles
    float xsq_s[2][128];
    float curD[8][8][32];               // running top-32 per (warp, query)
    int   curI[8][8][32];
    unsigned long long list[8][8][CAPk];
    int   cnt[8][8];
};
constexpr int SMEM_KNN = (int)sizeof(KnnSmem);

// merge list into curD/curI; returns new threshold (lane-31 value, all lanes)
__device__ __forceinline__ float reselect(KnnSmem* sm, int w, int qi, int lane) {
    float cd = sm->curD[w][qi][lane];
    int   ci = sm->curI[w][qi][lane];
    int n = sm->cnt[w][qi];
    for (int base = 0; base < n; base += 32) {
        float bd = EMPTYV; int bi = 0x7fffffff;
        if (base + lane < n) {
            unsigned long long e = sm->list[w][qi][base + lane];
            bd = __uint_as_float((unsigned)e);
            bi = (int)(unsigned)(e >> 32);
        }
        mergeTop(cd, ci, bd, bi, lane);
    }
    sm->curD[w][qi][lane] = cd;
    sm->curI[w][qi][lane] = ci;
    sm->cnt[w][qi] = 0;
    return __shfl_sync(FULLMASK, cd, 31);
}

// rare push path; returns (possibly refreshed) threshold
__device__ __noinline__ float pushSlow(KnnSmem* sm, int w, int qi, int lane,
                                       float thr, float d0, float d1, float d2,
                                       float d3, int nbase) {
#pragma unroll
    for (int s2 = 0; s2 < 4; ++s2) {
        float dv = (s2 == 0) ? d0 : (s2 == 1) ? d1 : (s2 == 2) ? d2 : d3;
        bool beat = dv < thr;
        unsigned bm = __ballot_sync(FULLMASK, beat);
        if (bm) {
            int c0 = sm->cnt[w][qi];
            if (beat) {
                int rank = __popc(bm & ((1u << lane) - 1));
                unsigned long long e =
                    ((unsigned long long)(unsigned)(nbase + s2 * 32 + lane) << 32)
                  | (unsigned long long)__float_as_uint(dv);
                sm->list[w][qi][c0 + rank] = e;
            }
            int c1 = c0 + __popc(bm);
            sm->cnt[w][qi] = c1;
            if (c1 >= 32) thr = reselect(sm, w, qi, lane);
        }
    }
    return thr;
}

__global__ __launch_bounds__(256, 2) void knn_kernel(const float* __restrict__ x,
                                                     const int* __restrict__ sidx) {
    extern __shared__ char smem_raw[];
    KnnSmem* sm = (KnnSmem*)smem_raw;

    int b = blockIdx.x >> 5;                 // 32 blocks per batch
    int qbase = (blockIdx.x & 31) * 64;
    int tid = threadIdx.x, lane = tid & 31, w = tid >> 5;
    int wq = w * 8;

    // init selection state
    if (tid < 64) sm->cnt[tid >> 3][tid & 7] = 0;
    for (int t = tid; t < 8 * 8 * 32; t += 256) {
        ((float*)sm->curD)[t] = EMPTYV;
        ((int*)sm->curI)[t] = 0;
    }

    // gather 64 queries directly into transposed qt2 + per-query sq
#pragma unroll
    for (int it = 0; it < 2; ++it) {
        int idx = tid + it * 256;
        int q = idx >> 3, p = idx & 7;
        int row = sidx[b * Sc + qbase + q];
        float4 v = *(const float4*)(x + ((size_t)(b * Nc + row)) * Fc + p * 4);
        sm->qt2[(4 * p + 0) * QSTRIDE + q] = v.x;
        sm->qt2[(4 * p + 1) * QSTRIDE + q] = v.y;
        sm->qt2[(4 * p + 2) * QSTRIDE + q] = v.z;
        sm->qt2[(4 * p + 3) * QSTRIDE + q] = v.w;
        float part = v.x * v.x + v.y * v.y + v.z * v.z + v.w * v.w;
        part += __shfl_xor_sync(FULLMASK, part, 1);
        part += __shfl_xor_sync(FULLMASK, part, 2);
        part += __shfl_xor_sync(FULLMASK, part, 4);
        if (p == 0) sm->sq_s[q] = part;
    }

    // prologue: load tile 0
    {
#pragma unroll
        for (int it = 0; it < 4; ++it) {
            int t = tid + it * 256;
            int r = t >> 3, p = t & 7;
            float4 v = *(const float4*)(x + ((size_t)(b * Nc + r)) * Fc + p * 4);
            int off = r * 128 + p * 16;
            off ^= (off >> 3) & 0x70;
            *(float4*)((char*)sm->xb[0] + off) = v;
        }
        if (tid < 128) sm->xsq_s[0][tid] = g_xsq[b * Nc + tid];
    }
    __syncthreads();

    float sqv[8], tr[8];
#pragma unroll
    for (int qi = 0; qi < 8; ++qi) { sqv[qi] = sm->sq_s[wq + qi]; tr[qi] = EMPTYV; }

    for (int t = 0; t < 128; ++t) {
        int cur = t & 1, nxt = cur ^ 1;
        // prefetch next tile into the other buffer (overlaps with compute)
        if (t + 1 < 128) {
            int n1 = (t + 1) * 128;
#pragma unroll
            for (int it = 0; it < 4; ++it) {
                int tt = tid + it * 256;
                int r = tt >> 3, p = tt & 7;
                float4 v = *(const float4*)(x + ((size_t)(b * Nc + n1 + r)) * Fc + p * 4);
                int off = r * 128 + p * 16;
                off ^= (off >> 3) & 0x70;
                *(float4*)((char*)sm->xb[nxt] + off) = v;
            }
            if (tid < 128) sm->xsq_s[nxt][tid] = g_xsq[b * Nc + n1 + tid];
        }

        // ---- dot products on current tile
        const float* xbc = sm->xb[cur];
        unsigned long long acc2[4][4];
#pragma unroll
        for (int m = 0; m < 4; ++m)
#pragma unroll
            for (int s2 = 0; s2 < 4; ++s2) acc2[m][s2] = 0ULL;

#pragma unroll
        for (int p = 0; p < 8; ++p) {
            unsigned long long qp[4][4];
#pragma unroll
            for (int j = 0; j < 4; ++j) {
                ulonglong2 qa = *(const ulonglong2*)&sm->qt2[(4 * p + j) * QSTRIDE + wq];
                ulonglong2 qb = *(const ulonglong2*)&sm->qt2[(4 * p + j) * QSTRIDE + wq + 4];
                qp[j][0] = qa.x; qp[j][1] = qa.y;
                qp[j][2] = qb.x; qp[j][3] = qb.y;
            }
#pragma unroll
            for (int s2 = 0; s2 < 4; ++s2) {
                int c = s2 * 32 + lane;
                int off = c * 128 + p * 16;
                off ^= (off >> 3) & 0x70;
                float4 xv = *(const float4*)((const char*)xbc + off);
                const float xe[4] = {xv.x, xv.y, xv.z, xv.w};
#pragma unroll
                for (int j = 0; j < 4; ++j) {
                    unsigned long long xs = splat2(xe[j]);
#pragma unroll
                    for (int m = 0; m < 4; ++m) fma2(acc2[m][s2], qp[j][m], xs);
                }
            }
        }

        float xq[4];
#pragma unroll
        for (int s2 = 0; s2 < 4; ++s2) xq[s2] = sm->xsq_s[cur][s2 * 32 + lane];
        int nbase = t * 128;

        // ---- selection: 1 ballot per query steady-state
#pragma unroll
        for (int m = 0; m < 4; ++m) {
            float2 av0 = unpack2(acc2[m][0]);
            float2 av1 = unpack2(acc2[m][1]);
            float2 av2 = unpack2(acc2[m][2]);
            float2 av3 = unpack2(acc2[m][3]);
#pragma unroll
            for (int h = 0; h < 2; ++h) {
                int qi = 2 * m + h;
                float a0 = h ? av0.y : av0.x;
                float a1 = h ? av1.y : av1.x;
                float a2 = h ? av2.y : av2.x;
                float a3 = h ? av3.y : av3.x;
                float d0 = sqv[qi] + xq[0] - 2.f * a0;
                float d1 = sqv[qi] + xq[1] - 2.f * a1;
                float d2 = sqv[qi] + xq[2] - 2.f * a2;
                float d3 = sqv[qi] + xq[3] - 2.f * a3;
                float dmin = fminf(fminf(d0, d1), fminf(d2, d3));
                if (__ballot_sync(FULLMASK, dmin < tr[qi])) {
                    tr[qi] = pushSlow(sm, w, qi, lane, tr[qi],
                                      d0, d1, d2, d3, nbase);
                }
            }
        }
        __syncthreads();   // next tile visible; current buffers free
    }

    // final flush + write neighbor indices
#pragma unroll 1
    for (int qi = 0; qi < 8; ++qi) {
        if (sm->cnt[w][qi] > 0) reselect(sm, w, qi, lane);
        g_knn[(b * Sc + qbase + wq + qi) * Kc + lane] = sm->curI[w][qi][lane];
    }
}

// ---------------------------------------------------------------------------
// Kernel 4: gather neighbors, 2-layer pointwise MLP, max-pool over K.
// 512 threads = 16 warps; 4 queries/block; warp w -> query w>>2,
// neighbors (w&3)*8 .. +7.  Packed fp32x2; h round-trips through a
// warp-private smem patch read back as uniform LDS.128 -> zero shuffles.
// ---------------------------------------------------------------------------
constexpr int GT_STRIDE = 36;
struct MlpSmem {
    float4 W1i[32 * 32];     // [f][lane] -> chans l, l+32, l+64, l+96
    float4 W2i[128 * 32];    // [o][lane]
    float4 b1i[32];
    float  gt[4][32][GT_STRIDE];   // [query][f][k]
    float  hsm[16][128 * 8];       // per warp: [o][k(8)]
    float  red[4][4][128];         // [query][warp-in-query][chan]
};
constexpr int SMEM_MLP = (int)sizeof(MlpSmem);

__global__ __launch_bounds__(512, 1) void mlp_kernel(const float* __restrict__ x,
                                                     const float* __restrict__ W1,
                                                     const float* __restrict__ b1,
                                                     const float* __restrict__ W2,
                                                     const float* __restrict__ b2,
                                                     float* __restrict__ feat) {
    extern __shared__ char smem_raw[];
    MlpSmem* sm = (MlpSmem*)smem_raw;

    int tid = threadIdx.x, lane = tid & 31, w = tid >> 5;
    int q = w >> 2, kb = (w & 3) * 8;

    for (int t = tid; t < 4096; t += 512) {
        int f = t >> 7, l = (t >> 2) & 31, j = t & 3;
        ((float*)&sm->W1i[f * 32 + l])[j] = W1[(l + 32 * j) * Fc + f];
    }
    for (int t = tid; t < 16384; t += 512) {
        int o = t >> 7, l = (t >> 2) & 31, j = t & 3;
        ((float*)&sm->W2i[o * 32 + l])[j] = W2[(l + 32 * j) * OUTc + o];
    }
    if (tid < 32)
        sm->b1i[tid] = make_float4(b1[tid], b1[tid + 32], b1[tid + 64], b1[tid + 96]);

    for (int grp = blockIdx.x; grp < (Bc * Sc) / 4; grp += gridDim.x) {
        __syncthreads();   // weights visible (1st iter) + gt/hsm/red reuse
#pragma unroll
        for (int it = 0; it < 2; ++it) {
            int idx = tid + it * 512;
            int q2 = idx >> 8, k = (idx >> 3) & 31, p = idx & 7;
            int qg = grp * 4 + q2;
            int bq = qg >> 11;
            int row = g_knn[qg * Kc + k];
            float4 v = *(const float4*)(x + ((size_t)(bq * Nc + row)) * Fc + p * 4);
            sm->gt[q2][4 * p + 0][k] = v.x;
            sm->gt[q2][4 * p + 1][k] = v.y;
            sm->gt[q2][4 * p + 2][k] = v.z;
            sm->gt[q2][4 * p + 3][k] = v.w;
        }
        __syncthreads();

        // ---- layer 1
        unsigned long long h2[4][4];   // [chan c][k-pair j]
        {
            float4 bb = sm->b1i[lane];
            const float be[4] = {bb.x, bb.y, bb.z, bb.w};
#pragma unroll
            for (int c = 0; c < 4; ++c) {
                unsigned long long bs = splat2(be[c]);
#pragma unroll
                for (int j = 0; j < 4; ++j) h2[c][j] = bs;
            }
#pragma unroll
            for (int f = 0; f < 32; ++f) {
                ulonglong2 g0 = *(const ulonglong2*)&sm->gt[q][f][kb];
                ulonglong2 g1 = *(const ulonglong2*)&sm->gt[q][f][kb + 4];
                float4 w1 = sm->W1i[f * 32 + lane];
                const float we[4] = {w1.x, w1.y, w1.z, w1.w};
#pragma unroll
                for (int c = 0; c < 4; ++c) {
                    unsigned long long ws = splat2(we[c]);
                    fma2(h2[c][0], ws, g0.x);
                    fma2(h2[c][1], ws, g0.y);
                    fma2(h2[c][2], ws, g1.x);
                    fma2(h2[c][3], ws, g1.y);
                }
            }
        }
        float* hw = sm->hsm[w];
#pragma unroll
        for (int c = 0; c < 4; ++c) {
            float2 p0 = unpack2(h2[c][0]);
            float2 p1 = unpack2(h2[c][1]);
            float2 p2 = unpack2(h2[c][2]);
            float2 p3 = unpack2(h2[c][3]);
            float4 va = make_float4(fmaxf(p0.x, 0.f), fmaxf(p0.y, 0.f),
                                    fmaxf(p1.x, 0.f), fmaxf(p1.y, 0.f));
            float4 vb = make_float4(fmaxf(p2.x, 0.f), fmaxf(p2.y, 0.f),
                                    fmaxf(p3.x, 0.f), fmaxf(p3.y, 0.f));
            *(float4*)&hw[(lane + 32 * c) * 8]     = va;
            *(float4*)&hw[(lane + 32 * c) * 8 + 4] = vb;
        }
        __syncwarp();

        // ---- layer 2 + maxpool over k
        unsigned long long y2[4][4];
#pragma unroll
        for (int c = 0; c < 4; ++c)
#pragma unroll
            for (int j = 0; j < 4; ++j) y2[c][j] = 0ULL;
#pragma unroll 4
        for (int o = 0; o < 128; ++o) {
            ulonglong2 hp0 = *(const ulonglong2*)&hw[o * 8];       // uniform
            ulonglong2 hp1 = *(const ulonglong2*)&hw[o * 8 + 4];   // uniform
            float4 w2 = sm->W2i[o * 32 + lane];
            const float we[4] = {w2.x, w2.y, w2.z, w2.w};
#pragma unroll
            for (int c = 0; c < 4; ++c) {
                unsigned long long ws = splat2(we[c]);
                fma2(y2[c][0], ws, hp0.x);
                fma2(y2[c][1], ws, hp0.y);
                fma2(y2[c][2], ws, hp1.x);
                fma2(y2[c][3], ws, hp1.y);
            }
        }
#pragma unroll
        for (int c = 0; c < 4; ++c) {
            float2 a0 = unpack2(y2[c][0]);
            float2 a1 = unpack2(y2[c][1]);
            float2 a2 = unpack2(y2[c][2]);
            float2 a3 = unpack2(y2[c][3]);
            float m = fmaxf(fmaxf(fmaxf(a0.x, a0.y), fmaxf(a1.x, a1.y)),
                            fmaxf(fmaxf(a2.x, a2.y), fmaxf(a3.x, a3.y)));
            sm->red[q][w & 3][lane + 32 * c] = m;
        }
        __syncthreads();

        {
            int q2 = tid >> 7, o = tid & 127;
            float v = sm->red[q2][0][o];
#pragma unroll
            for (int ww = 1; ww < 4; ++ww) v = fmaxf(v, sm->red[q2][ww][o]);
            int qg = grp * 4 + q2;
            int bq = qg >> 11, s = qg & 2047;
            feat[((size_t)bq * OUTc + o) * Sc + s] = v + b2[o];
        }
    }
}

// ---------------------------------------------------------------------------
extern "C" void kernel_launch(void* const* d_in, const int* in_sizes, int n_in,
                              void* d_out, int out_size) {
    const float* x    = (const float*)d_in[0];
    const int*   sidx = (const int*)d_in[1];
    const float* W1   = (const float*)d_in[2];
    const float* b1   = (const float*)d_in[3];
    const float* W2   = (const float*)d_in[4];
    const float* b2   = (const float*)d_in[5];
    float* out  = (float*)d_out;
    float* feat = out;                                  // [B, OUT, S]
    float* samp = out + (size_t)Bc * OUTc * Sc;         // [B, F, S]

    xsq_kernel<<<(Bc * Nc) / 256, 256>>>(x);
    sampled_kernel<<<(Bc * Fc * Sc) / 256, 256>>>(x, sidx, samp);

    cudaFuncSetAttribute(knn_kernel, cudaFuncAttributeMaxDynamicSharedMemorySize, SMEM_KNN);
    knn_kernel<<<(Bc * Sc) / 64, 256, SMEM_KNN>>>(x, sidx);

    cudaFuncSetAttribute(mlp_kernel, cudaFuncAttributeMaxDynamicSharedMemorySize, SMEM_MLP);
    mlp_kernel<<<148, 512, SMEM_MLP>>>(x, W1, b1, W2, b2, feat);
}

// round 6
// speedup vs baseline: 3.3273x; 1.0261x over previous
#include <cuda_runtime.h>
#include <cuda_bf16.h>
#include <cstdint>

#define FULLMASK 0xffffffffu
#define EMPTYV 3.402823466e38f

constexpr int Bc = 8, Nc = 16384, Fc = 32, Sc = 2048, Kc = 32, OUTc = 128;

// Scratch (device globals: allocation-free)
__device__ float g_xsq[Bc * Nc];
__device__ int   g_knn[Bc * Sc * Kc];

// ---------------------------------------------------------------------------
// Packed fp32x2 helpers
// ---------------------------------------------------------------------------
__device__ __forceinline__ unsigned long long splat2(float v) {
    unsigned long long r;
    asm("mov.b64 %0, {%1, %1};" : "=l"(r) : "r"(__float_as_uint(v)));
    return r;
}
__device__ __forceinline__ void fma2(unsigned long long& d,
                                     unsigned long long a,
                                     unsigned long long b) {
    asm("fma.rn.f32x2 %0, %1, %2, %0;" : "+l"(d) : "l"(a), "l"(b));
}
__device__ __forceinline__ float2 unpack2(unsigned long long v) {
    unsigned int lo, hi;
    asm("mov.b64 {%0, %1}, %2;" : "=r"(lo), "=r"(hi) : "l"(v));
    return make_float2(__uint_as_float(lo), __uint_as_float(hi));
}

// ---------------------------------------------------------------------------
// cp.async helpers (LDGSTS)
// ---------------------------------------------------------------------------
__device__ __forceinline__ void cpasync16(void* dst, const void* src) {
    uint32_t d = (uint32_t)__cvta_generic_to_shared(dst);
    asm volatile("cp.async.ca.shared.global [%0], [%1], 16;" :: "r"(d), "l"(src));
}
__device__ __forceinline__ void cpasync4(void* dst, const void* src) {
    uint32_t d = (uint32_t)__cvta_generic_to_shared(dst);
    asm volatile("cp.async.ca.shared.global [%0], [%1], 4;" :: "r"(d), "l"(src));
}
__device__ __forceinline__ void cpasync_commit() {
    asm volatile("cp.async.commit_group;");
}
__device__ __forceinline__ void cpasync_wait0() {
    asm volatile("cp.async.wait_group 0;" ::: "memory");
}

// ---------------------------------------------------------------------------
// Kernel 1: x_sq
// ---------------------------------------------------------------------------
__global__ void xsq_kernel(const float* __restrict__ x) {
    int i = blockIdx.x * blockDim.x + threadIdx.x;
    if (i >= Bc * Nc) return;
    const float4* p = (const float4*)(x + (size_t)i * Fc);
    float s = 0.f;
#pragma unroll
    for (int c = 0; c < 8; ++c) {
        float4 v = p[c];
        s += v.x * v.x + v.y * v.y + v.z * v.z + v.w * v.w;
    }
    g_xsq[i] = s;
}

// ---------------------------------------------------------------------------
// Kernel 2: sampled_batch output [B, F, S]
// ---------------------------------------------------------------------------
__global__ void sampled_kernel(const float* __restrict__ x,
                               const int* __restrict__ sidx,
                               float* __restrict__ out2) {
    int i = blockIdx.x * blockDim.x + threadIdx.x;
    if (i >= Bc * Fc * Sc) return;
    int b = i / (Fc * Sc);
    int r = i - b * Fc * Sc;
    int f = r / Sc;
    int s = r - f * Sc;
    int row = sidx[b * Sc + s];
    out2[i] = x[((size_t)(b * Nc + row)) * Fc + f];
}

// ---------------------------------------------------------------------------
// Warp-level bitonic helpers
// ---------------------------------------------------------------------------
__device__ __forceinline__ void cmpSwap(float& d, int& i, int j, bool dirAsc, int lane) {
    float od = __shfl_xor_sync(FULLMASK, d, j);
    int   oi = __shfl_xor_sync(FULLMASK, i, j);
    bool lower = ((lane & j) == 0);
    bool less = (d < od) || (d == od && i < oi);
    bool keep = dirAsc ? (lower == less) : (lower != less);
    if (!keep) { d = od; i = oi; }
}

__device__ __forceinline__ void sortDesc32(float& d, int& i, int lane) {
#pragma unroll
    for (int k = 2; k <= 32; k <<= 1) {
#pragma unroll
        for (int j = k >> 1; j > 0; j >>= 1) {
            bool asc = ((lane & k) == 0);
            cmpSwap(d, i, j, !asc, lane);
        }
    }
}

__device__ __forceinline__ void mergeTop(float& cd, int& ci, float& bd, int& bi, int lane) {
    sortDesc32(bd, bi, lane);
    bool takeNew = (bd < cd) || (bd == cd && bi < ci);
    float nd = takeNew ? bd : cd;
    int   ni = takeNew ? bi : ci;
#pragma unroll
    for (int j = 16; j > 0; j >>= 1) cmpSwap(nd, ni, j, true, lane);
    cd = nd; ci = ni;
}

// ---------------------------------------------------------------------------
// Kernel 3: fused distance + top-K
// Block: 256 thr, 8 warps, 8 queries/warp, 64 queries/block, 256 blocks.
// ---------------------------------------------------------------------------
constexpr int QSTRIDE = 68;   // padded row stride (floats) for qt2
constexpr int CAPk = 64;      // overflow-list capacity per query

struct KnnSmem {
    float qt2[32 * QSTRIDE];            // [f][q] transposed, padded
    float sq_s[64];
    float xb[2][128 * 32];              // double-buffered swizzled tiles
    float xsq_s[2][128];
    float curD[8][8][32];               // running top-32 per (warp, query)
    int   curI[8][8][32];
    unsigned long long list[8][8][CAPk];
    int   cnt[8][8];
};
constexpr int SMEM_KNN = (int)sizeof(KnnSmem);

// merge list into curD/curI; returns new threshold (lane-31 value, all lanes)
__device__ __forceinline__ float reselect(KnnSmem* sm, int w, int qi, int lane) {
    float cd = sm->curD[w][qi][lane];
    int   ci = sm->curI[w][qi][lane];
    int n = sm->cnt[w][qi];
    for (int base = 0; base < n; base += 32) {
        float bd = EMPTYV; int bi = 0x7fffffff;
        if (base + lane < n) {
            unsigned long long e = sm->list[w][qi][base + lane];
            bd = __uint_as_float((unsigned)e);
            bi = (int)(unsigned)(e >> 32);
        }
        mergeTop(cd, ci, bd, bi, lane);
    }
    sm->curD[w][qi][lane] = cd;
    sm->curI[w][qi][lane] = ci;
    sm->cnt[w][qi] = 0;
    return __shfl_sync(FULLMASK, cd, 31);
}

// rare push path; returns (possibly refreshed) threshold
__device__ __noinline__ float pushSlow(KnnSmem* sm, int w, int qi, int lane,
                                       float thr, float d0, float d1, float d2,
                                       float d3, int nbase) {
#pragma unroll
    for (int s2 = 0; s2 < 4; ++s2) {
        float dv = (s2 == 0) ? d0 : (s2 == 1) ? d1 : (s2 == 2) ? d2 : d3;
        bool beat = dv < thr;
        unsigned bm = __ballot_sync(FULLMASK, beat);
        if (bm) {
            int c0 = sm->cnt[w][qi];
            if (beat) {
                int rank = __popc(bm & ((1u << lane) - 1));
                unsigned long long e =
                    ((unsigned long long)(unsigned)(nbase + s2 * 32 + lane) << 32)
                  | (unsigned long long)__float_as_uint(dv);
                sm->list[w][qi][c0 + rank] = e;
            }
            int c1 = c0 + __popc(bm);
            sm->cnt[w][qi] = c1;
            if (c1 >= 32) thr = reselect(sm, w, qi, lane);
        }
    }
    return thr;
}

__global__ __launch_bounds__(256, 2) void knn_kernel(const float* __restrict__ x,
                                                     const int* __restrict__ sidx) {
    extern __shared__ char smem_raw[];
    KnnSmem* sm = (KnnSmem*)smem_raw;

    int b = blockIdx.x >> 5;                 // 32 blocks per batch
    int qbase = (blockIdx.x & 31) * 64;
    int tid = threadIdx.x, lane = tid & 31, w = tid >> 5;
    int wq = w * 8;

    // init selection state
    if (tid < 64) sm->cnt[tid >> 3][tid & 7] = 0;
    for (int t = tid; t < 8 * 8 * 32; t += 256) {
        ((float*)sm->curD)[t] = EMPTYV;
        ((int*)sm->curI)[t] = 0;
    }

    // prologue: async-load tile 0
    {
#pragma unroll
        for (int it = 0; it < 4; ++it) {
            int t = tid + it * 256;
            int r = t >> 3, p = t & 7;
            int off = r * 128 + p * 16;
            off ^= (off >> 3) & 0x70;
            cpasync16((char*)sm->xb[0] + off,
                      x + ((size_t)(b * Nc + r)) * Fc + p * 4);
        }
        if (tid < 128) cpasync4(&sm->xsq_s[0][tid], &g_xsq[b * Nc + tid]);
        cpasync_commit();
    }

    // gather 64 queries into transposed qt2 + per-query sq (overlaps cp.async)
#pragma unroll
    for (int it = 0; it < 2; ++it) {
        int idx = tid + it * 256;
        int q = idx >> 3, p = idx & 7;
        int row = sidx[b * Sc + qbase + q];
        float4 v = *(const float4*)(x + ((size_t)(b * Nc + row)) * Fc + p * 4);
        sm->qt2[(4 * p + 0) * QSTRIDE + q] = v.x;
        sm->qt2[(4 * p + 1) * QSTRIDE + q] = v.y;
        sm->qt2[(4 * p + 2) * QSTRIDE + q] = v.z;
        sm->qt2[(4 * p + 3) * QSTRIDE + q] = v.w;
        float part = v.x * v.x + v.y * v.y + v.z * v.z + v.w * v.w;
        part += __shfl_xor_sync(FULLMASK, part, 1);
        part += __shfl_xor_sync(FULLMASK, part, 2);
        part += __shfl_xor_sync(FULLMASK, part, 4);
        if (p == 0) sm->sq_s[q] = part;
    }
    cpasync_wait0();
    __syncthreads();

    float sqv[8], tr[8];
#pragma unroll
    for (int qi = 0; qi < 8; ++qi) { sqv[qi] = sm->sq_s[wq + qi]; tr[qi] = EMPTYV; }

    for (int t = 0; t < 128; ++t) {
        int cur = t & 1, nxt = cur ^ 1;
        // async prefetch next tile (no registers held, no STS stalls)
        if (t + 1 < 128) {
            int n1 = (t + 1) * 128;
#pragma unroll
            for (int it = 0; it < 4; ++it) {
                int tt = tid + it * 256;
                int r = tt >> 3, p = tt & 7;
                int off = r * 128 + p * 16;
                off ^= (off >> 3) & 0x70;
                cpasync16((char*)sm->xb[nxt] + off,
                          x + ((size_t)(b * Nc + n1 + r)) * Fc + p * 4);
            }
            if (tid < 128) cpasync4(&sm->xsq_s[nxt][tid], &g_xsq[b * Nc + n1 + tid]);
        }
        cpasync_commit();

        // ---- dot products on current tile
        const float* xbc = sm->xb[cur];
        unsigned long long acc2[4][4];
#pragma unroll
        for (int m = 0; m < 4; ++m)
#pragma unroll
            for (int s2 = 0; s2 < 4; ++s2) acc2[m][s2] = 0ULL;

#pragma unroll
        for (int p = 0; p < 8; ++p) {
            unsigned long long qp[4][4];
#pragma unroll
            for (int j = 0; j < 4; ++j) {
                ulonglong2 qa = *(const ulonglong2*)&sm->qt2[(4 * p + j) * QSTRIDE + wq];
                ulonglong2 qb = *(const ulonglong2*)&sm->qt2[(4 * p + j) * QSTRIDE + wq + 4];
                qp[j][0] = qa.x; qp[j][1] = qa.y;
                qp[j][2] = qb.x; qp[j][3] = qb.y;
            }
#pragma unroll
            for (int s2 = 0; s2 < 4; ++s2) {
                int c = s2 * 32 + lane;
                int off = c * 128 + p * 16;
                off ^= (off >> 3) & 0x70;
                float4 xv = *(const float4*)((const char*)xbc + off);
                const float xe[4] = {xv.x, xv.y, xv.z, xv.w};
#pragma unroll
                for (int j = 0; j < 4; ++j) {
                    unsigned long long xs = splat2(xe[j]);
#pragma unroll
                    for (int m = 0; m < 4; ++m) fma2(acc2[m][s2], qp[j][m], xs);
                }
            }
        }

        float xq[4];
#pragma unroll
        for (int s2 = 0; s2 < 4; ++s2) xq[s2] = sm->xsq_s[cur][s2 * 32 + lane];
        int nbase = t * 128;

        // ---- selection: 1 ballot per query steady-state
#pragma unroll
        for (int m = 0; m < 4; ++m) {
            float2 av0 = unpack2(acc2[m][0]);
            float2 av1 = unpack2(acc2[m][1]);
            float2 av2 = unpack2(acc2[m][2]);
            float2 av3 = unpack2(acc2[m][3]);
#pragma unroll
            for (int h = 0; h < 2; ++h) {
                int qi = 2 * m + h;
                float a0 = h ? av0.y : av0.x;
                float a1 = h ? av1.y : av1.x;
                float a2 = h ? av2.y : av2.x;
                float a3 = h ? av3.y : av3.x;
                float d0 = sqv[qi] + xq[0] - 2.f * a0;
                float d1 = sqv[qi] + xq[1] - 2.f * a1;
                float d2 = sqv[qi] + xq[2] - 2.f * a2;
                float d3 = sqv[qi] + xq[3] - 2.f * a3;
                float dmin = fminf(fminf(d0, d1), fminf(d2, d3));
                if (__ballot_sync(FULLMASK, dmin < tr[qi])) {
                    tr[qi] = pushSlow(sm, w, qi, lane, tr[qi],
                                      d0, d1, d2, d3, nbase);
                }
            }
        }
        cpasync_wait0();
        __syncthreads();   // next tile visible; current buffers free
    }

    // final flush + write neighbor indices
#pragma unroll 1
    for (int qi = 0; qi < 8; ++qi) {
        if (sm->cnt[w][qi] > 0) reselect(sm, w, qi, lane);
        g_knn[(b * Sc + qbase + wq + qi) * Kc + lane] = sm->curI[w][qi][lane];
    }
}

// ---------------------------------------------------------------------------
// Kernel 4: gather neighbors, 2-layer pointwise MLP, max-pool over K.
// 512 threads = 16 warps; 4 queries/block; warp w -> query w>>2,
// neighbors (w&3)*8 .. +7.
// ---------------------------------------------------------------------------
constexpr int GT_STRIDE = 36;
struct MlpSmem {
    float4 W1i[32 * 32];     // [f][lane] -> chans l, l+32, l+64, l+96
    float4 W2i[128 * 32];    // [o][lane]
    float4 b1i[32];
    float  gt[4][32][GT_STRIDE];   // [query][f][k]
    float  hsm[16][128 * 8];       // per warp: [o][k(8)]
    float  red[4][4][128];         // [query][warp-in-query][chan]
};
constexpr int SMEM_MLP = (int)sizeof(MlpSmem);

__global__ __launch_bounds__(512, 1) void mlp_kernel(const float* __restrict__ x,
                                                     const float* __restrict__ W1,
                                                     const float* __restrict__ b1,
                                                     const float* __restrict__ W2,
                                                     const float* __restrict__ b2,
                                                     float* __restrict__ feat) {
    extern __shared__ char smem_raw[];
    MlpSmem* sm = (MlpSmem*)smem_raw;

    int tid = threadIdx.x, lane = tid & 31, w = tid >> 5;
    int q = w >> 2, kb = (w & 3) * 8;

    for (int t = tid; t < 4096; t += 512) {
        int f = t >> 7, l = (t >> 2) & 31, j = t & 3;
        ((float*)&sm->W1i[f * 32 + l])[j] = W1[(l + 32 * j) * Fc + f];
    }
    for (int t = tid; t < 16384; t += 512) {
        int o = t >> 7, l = (t >> 2) & 31, j = t & 3;
        ((float*)&sm->W2i[o * 32 + l])[j] = W2[(l + 32 * j) * OUTc + o];
    }
    if (tid < 32)
        sm->b1i[tid] = make_float4(b1[tid], b1[tid + 32], b1[tid + 64], b1[tid + 96]);

    for (int grp = blockIdx.x; grp < (Bc * Sc) / 4; grp += gridDim.x) {
        __syncthreads();   // weights visible (1st iter) + gt/hsm/red reuse
#pragma unroll
        for (int it = 0; it < 2; ++it) {
            int idx = tid + it * 512;
            int q2 = idx >> 8, k = (idx >> 3) & 31, p = idx & 7;
            int qg = grp * 4 + q2;
            int bq = qg >> 11;
            int row = g_knn[qg * Kc + k];
            float4 v = *(const float4*)(x + ((size_t)(bq * Nc + row)) * Fc + p * 4);
            sm->gt[q2][4 * p + 0][k] = v.x;
            sm->gt[q2][4 * p + 1][k] = v.y;
            sm->gt[q2][4 * p + 2][k] = v.z;
            sm->gt[q2][4 * p + 3][k] = v.w;
        }
        __syncthreads();

        // ---- layer 1
        unsigned long long h2[4][4];   // [chan c][k-pair j]
        {
            float4 bb = sm->b1i[lane];
            const float be[4] = {bb.x, bb.y, bb.z, bb.w};
#pragma unroll
            for (int c = 0; c < 4; ++c) {
                unsigned long long bs = splat2(be[c]);
#pragma unroll
                for (int j = 0; j < 4; ++j) h2[c][j] = bs;
            }
#pragma unroll
            for (int f = 0; f < 32; ++f) {
                ulonglong2 g0 = *(const ulonglong2*)&sm->gt[q][f][kb];
                ulonglong2 g1 = *(const ulonglong2*)&sm->gt[q][f][kb + 4];
                float4 w1 = sm->W1i[f * 32 + lane];
                const float we[4] = {w1.x, w1.y, w1.z, w1.w};
#pragma unroll
                for (int c = 0; c < 4; ++c) {
                    unsigned long long ws = splat2(we[c]);
                    fma2(h2[c][0], ws, g0.x);
                    fma2(h2[c][1], ws, g0.y);
                    fma2(h2[c][2], ws, g1.x);
                    fma2(h2[c][3], ws, g1.y);
                }
            }
        }
        float* hw = sm->hsm[w];
#pragma unroll
        for (int c = 0; c < 4; ++c) {
            float2 p0 = unpack2(h2[c][0]);
            float2 p1 = unpack2(h2[c][1]);
            float2 p2 = unpack2(h2[c][2]);
            float2 p3 = unpack2(h2[c][3]);
            float4 va = make_float4(fmaxf(p0.x, 0.f), fmaxf(p0.y, 0.f),
                                    fmaxf(p1.x, 0.f), fmaxf(p1.y, 0.f));
            float4 vb = make_float4(fmaxf(p2.x, 0.f), fmaxf(p2.y, 0.f),
                                    fmaxf(p3.x, 0.f), fmaxf(p3.y, 0.f));
            *(float4*)&hw[(lane + 32 * c) * 8]     = va;
            *(float4*)&hw[(lane + 32 * c) * 8 + 4] = vb;
        }
        __syncwarp();

        // ---- layer 2 + maxpool over k
        unsigned long long y2[4][4];
#pragma unroll
        for (int c = 0; c < 4; ++c)
#pragma unroll
            for (int j = 0; j < 4; ++j) y2[c][j] = 0ULL;
#pragma unroll 8
        for (int o = 0; o < 128; ++o) {
            ulonglong2 hp0 = *(const ulonglong2*)&hw[o * 8];       // uniform
            ulonglong2 hp1 = *(const ulonglong2*)&hw[o * 8 + 4];   // uniform
            float4 w2 = sm->W2i[o * 32 + lane];
            const float we[4] = {w2.x, w2.y, w2.z, w2.w};
#pragma unroll
            for (int c = 0; c < 4; ++c) {
                unsigned long long ws = splat2(we[c]);
                fma2(y2[c][0], ws, hp0.x);
                fma2(y2[c][1], ws, hp0.y);
                fma2(y2[c][2], ws, hp1.x);
                fma2(y2[c][3], ws, hp1.y);
            }
        }
#pragma unroll
        for (int c = 0; c < 4; ++c) {
            float2 a0 = unpack2(y2[c][0]);
            float2 a1 = unpack2(y2[c][1]);
            float2 a2 = unpack2(y2[c][2]);
            float2 a3 = unpack2(y2[c][3]);
            float m = fmaxf(fmaxf(fmaxf(a0.x, a0.y), fmaxf(a1.x, a1.y)),
                            fmaxf(fmaxf(a2.x, a2.y), fmaxf(a3.x, a3.y)));
            sm->red[q][w & 3][lane + 32 * c] = m;
        }
        __syncthreads();

        {
            int q2 = tid >> 7, o = tid & 127;
            float v = sm->red[q2][0][o];
#pragma unroll
            for (int ww = 1; ww < 4; ++ww) v = fmaxf(v, sm->red[q2][ww][o]);
            int qg = grp * 4 + q2;
            int bq = qg >> 11, s = qg & 2047;
            feat[((size_t)bq * OUTc + o) * Sc + s] = v + b2[o];
        }
    }
}

// ---------------------------------------------------------------------------
extern "C" void kernel_launch(void* const* d_in, const int* in_sizes, int n_in,
                              void* d_out, int out_size) {
    const float* x    = (const float*)d_in[0];
    const int*   sidx = (const int*)d_in[1];
    const float* W1   = (const float*)d_in[2];
    const float* b1   = (const float*)d_in[3];
    const float* W2   = (const float*)d_in[4];
    const float* b2   = (const float*)d_in[5];
    float* out  = (float*)d_out;
    float* feat = out;                                  // [B, OUT, S]
    float* samp = out + (size_t)Bc * OUTc * Sc;         // [B, F, S]

    xsq_kernel<<<(Bc * Nc) / 256, 256>>>(x);
    sampled_kernel<<<(Bc * Fc * Sc) / 256, 256>>>(x, sidx, samp);

    cudaFuncSetAttribute(knn_kernel, cudaFuncAttributeMaxDynamicSharedMemorySize, SMEM_KNN);
    knn_kernel<<<(Bc * Sc) / 64, 256, SMEM_KNN>>>(x, sidx);

    cudaFuncSetAttribute(mlp_kernel, cudaFuncAttributeMaxDynamicSharedMemorySize, SMEM_MLP);
    mlp_kernel<<<148, 512, SMEM_MLP>>>(x, W1, b1, W2, b2, feat);
}